// round 2
// baseline (speedup 1.0000x reference)
#include <cuda_runtime.h>
#include <cuda_bf16.h>

// Problem constants (fixed by dataset): N = 131072 neurons, E = N*64 edges.
#define MAX_N 131072

// Scratch: zero-initialized at module load; neuron kernel consumes AND re-zeros
// them each step so every graph replay starts from zero (deterministic).
__device__ float g_dge[MAX_N];
__device__ float g_dgi[MAX_N];
__device__ unsigned char g_code[MAX_N];   // 0 = no spike, 1 = exc spike, 2 = inh spike

// ---------------------------------------------------------------------------
// Kernel 1: build per-neuron spike code (1-byte gather table for edge pass).
// Bool inputs arrive as float32 (0.0 / 1.0).
// ---------------------------------------------------------------------------
__global__ void build_code_kernel(const float* __restrict__ spiked,
                                  const float* __restrict__ is_exc,
                                  int n) {
    int i = blockIdx.x * blockDim.x + threadIdx.x;
    if (i < n) {
        bool s = spiked[i] != 0.0f;
        unsigned char c = 0;
        if (s) c = (is_exc[i] != 0.0f) ? 1 : 2;
        g_code[i] = c;
    }
}

// ---------------------------------------------------------------------------
// Kernel 2: event-driven synaptic scatter.
// src stream read as int4 (4 edges/thread). dst + Q gathers + atomics only for
// the ~5% active edges.
// ---------------------------------------------------------------------------
__global__ void edge_kernel(const int* __restrict__ src,
                            const int* __restrict__ dst,
                            const float* __restrict__ Qge,
                            const float* __restrict__ Qgi,
                            int E) {
    int t = blockIdx.x * blockDim.x + threadIdx.x;
    int e = t * 4;
    if (e + 3 < E) {
        int4 s4 = *reinterpret_cast<const int4*>(src + e);
        int ss[4] = {s4.x, s4.y, s4.z, s4.w};
#pragma unroll
        for (int j = 0; j < 4; j++) {
            unsigned char c = g_code[ss[j]];
            if (c) {
                int d = __ldg(dst + e + j);
                if (c == 1) atomicAdd(&g_dge[d], __ldg(Qge + d));
                else        atomicAdd(&g_dgi[d], __ldg(Qgi + d));
            }
        }
    } else {
        for (; e < E; e++) {
            unsigned char c = g_code[src[e]];
            if (c) {
                int d = dst[e];
                if (c == 1) atomicAdd(&g_dge[d], Qge[d]);
                else        atomicAdd(&g_dgi[d], Qgi[d]);
            }
        }
    }
}

// ---------------------------------------------------------------------------
// Kernel 3: AdEx neuron update (pure elementwise), writes the 6 outputs and
// re-zeros the delta scratch for the next replay.
// ---------------------------------------------------------------------------
__global__ void neuron_kernel(
    const float* __restrict__ voltage, const float* __restrict__ adapt,
    const float* __restrict__ ge_in,   const float* __restrict__ gi_in,
    const float* __restrict__ stim,    const float* __restrict__ refr_in,
    const float* __restrict__ g_L,     const float* __restrict__ delta_T,
    const float* __restrict__ v_thresh,const float* __restrict__ v_rest,
    const float* __restrict__ C,       const float* __restrict__ a,
    const float* __restrict__ b,       const float* __restrict__ tau_w,
    const float* __restrict__ tau_ge,  const float* __restrict__ tau_gi,
    const float* __restrict__ E_ge,    const float* __restrict__ E_gi,
    const float* __restrict__ I_bias,  const float* __restrict__ stim_scale,
    const float* __restrict__ v_cut,   const float* __restrict__ v_reset,
    const float* __restrict__ t_refrac,
    const float* __restrict__ dt_ptr,
    float* __restrict__ out, int n) {
    int i = blockIdx.x * blockDim.x + threadIdx.x;
    if (i >= n) return;

    float dt = __ldg(dt_ptr);

    float v  = voltage[i];
    float w  = adapt[i];
    float ge = ge_in[i] + g_dge[i];
    float gi = gi_in[i] + g_dgi[i];
    g_dge[i] = 0.0f;
    g_dgi[i] = 0.0f;

    float gl = g_L[i];
    float dT = delta_T[i];
    float vr = v_rest[i];

    float I = I_bias[i] + stim_scale[i] * stim[i]
            + ge * (E_ge[i] - v) + gi * (E_gi[i] - v);
    float exp_term = gl * dT * expf(fminf((v - v_thresh[i]) / dT, 20.0f));
    float dv = (-gl * (v - vr) + exp_term - w + I) / C[i];
    float dw = (-w + a[i] * (v - vr)) / tau_w[i];

    float refr = refr_in[i];
    float vn = (refr <= 0.0f) ? (v + dv * dt) : v;
    float wn = w + dw * dt;
    float geo = ge - (ge / tau_ge[i]) * dt;
    float gio = gi - (gi / tau_gi[i]) * dt;

    bool spk = vn > v_cut[i];
    float vout = spk ? v_reset[i] : vn;
    float wout = spk ? (wn + b[i]) : wn;
    float rout = (spk ? t_refrac[i] : refr) - dt;

    out[0 * n + i] = vout;
    out[1 * n + i] = wout;
    out[2 * n + i] = geo;
    out[3 * n + i] = gio;
    out[4 * n + i] = rout;
    out[5 * n + i] = spk ? 1.0f : 0.0f;
}

extern "C" void kernel_launch(void* const* d_in, const int* in_sizes, int n_in,
                              void* d_out, int out_size) {
    const float* voltage    = (const float*)d_in[0];
    const float* adapt      = (const float*)d_in[1];
    const float* ge         = (const float*)d_in[2];
    const float* gi         = (const float*)d_in[3];
    const float* stim       = (const float*)d_in[4];
    const float* refr       = (const float*)d_in[5];
    const float* g_L        = (const float*)d_in[6];
    const float* delta_T    = (const float*)d_in[7];
    const float* v_thresh   = (const float*)d_in[8];
    const float* v_rest     = (const float*)d_in[9];
    const float* C          = (const float*)d_in[10];
    const float* a          = (const float*)d_in[11];
    const float* b          = (const float*)d_in[12];
    const float* tau_w      = (const float*)d_in[13];
    const float* tau_ge     = (const float*)d_in[14];
    const float* tau_gi     = (const float*)d_in[15];
    const float* E_ge       = (const float*)d_in[16];
    const float* E_gi       = (const float*)d_in[17];
    const float* I_bias     = (const float*)d_in[18];
    const float* stim_scale = (const float*)d_in[19];
    const float* Q_ge       = (const float*)d_in[20];
    const float* Q_gi       = (const float*)d_in[21];
    const float* v_cut      = (const float*)d_in[22];
    const float* v_reset    = (const float*)d_in[23];
    const float* t_refrac   = (const float*)d_in[24];
    const float* spiked     = (const float*)d_in[25];
    const float* is_exc     = (const float*)d_in[26];
    const int*   edge_index = (const int*)d_in[27];
    const float* dt         = (const float*)d_in[28];

    int n = in_sizes[0];
    int E = in_sizes[27] / 2;
    const int* src = edge_index;
    const int* dst = edge_index + E;

    build_code_kernel<<<(n + 255) / 256, 256>>>(spiked, is_exc, n);

    int edge_threads = (E + 3) / 4;
    edge_kernel<<<(edge_threads + 255) / 256, 256>>>(src, dst, Q_ge, Q_gi, E);

    neuron_kernel<<<(n + 255) / 256, 256>>>(
        voltage, adapt, ge, gi, stim, refr,
        g_L, delta_T, v_thresh, v_rest, C, a, b, tau_w, tau_ge, tau_gi,
        E_ge, E_gi, I_bias, stim_scale, v_cut, v_reset, t_refrac,
        dt, (float*)d_out, n);
}

// round 3
// speedup vs baseline: 1.0570x; 1.0570x over previous
#include <cuda_runtime.h>
#include <cuda_bf16.h>

// Problem constants (fixed by dataset): N = 131072 neurons, E = N*64 edges.
#define MAX_N 131072

// Scratch: zero-initialized at module load; neuron kernel consumes AND re-zeros
// them each step so every graph replay starts from zero (deterministic).
__device__ float g_dge[MAX_N];
__device__ float g_dgi[MAX_N];
// Packed spike code: 2 bits per neuron (0 = silent, 1 = exc spike, 2 = inh spike).
// 32 KB total -> L1-resident on every SM during the edge pass.
__device__ unsigned char g_pack[MAX_N / 4];

// ---------------------------------------------------------------------------
// Kernel 1: build packed per-neuron spike code. float4 loads, 4 neurons/thread.
// Bool inputs arrive as float32 (0.0 / 1.0).
// ---------------------------------------------------------------------------
__global__ void build_code_kernel(const float4* __restrict__ spiked4,
                                  const float4* __restrict__ is_exc4,
                                  int n4) {
    int i = blockIdx.x * blockDim.x + threadIdx.x;
    if (i >= n4) return;
    float4 s = spiked4[i];
    float4 x = is_exc4[i];
    unsigned int b = 0;
    b |= (s.x != 0.0f ? (x.x != 0.0f ? 1u : 2u) : 0u) << 0;
    b |= (s.y != 0.0f ? (x.y != 0.0f ? 1u : 2u) : 0u) << 2;
    b |= (s.z != 0.0f ? (x.z != 0.0f ? 1u : 2u) : 0u) << 4;
    b |= (s.w != 0.0f ? (x.w != 0.0f ? 1u : 2u) : 0u) << 6;
    g_pack[i] = (unsigned char)b;
}

// ---------------------------------------------------------------------------
// Kernel 2: event-driven synaptic scatter.
// src stream read as int4 (4 edges/thread). dst int4 loaded only when at least
// one of the 4 edges has an active source (~18.5% of groups). Q gathers +
// atomics only for the ~5% active edges.
// ---------------------------------------------------------------------------
__global__ void edge_kernel(const int* __restrict__ src,
                            const int* __restrict__ dst,
                            const float* __restrict__ Qge,
                            const float* __restrict__ Qgi,
                            int E) {
    int t = blockIdx.x * blockDim.x + threadIdx.x;
    int e = t * 4;
    if (e + 3 < E) {
        int4 s4 = *reinterpret_cast<const int4*>(src + e);
        int ss[4] = {s4.x, s4.y, s4.z, s4.w};
        unsigned int cc[4];
        unsigned int any = 0;
#pragma unroll
        for (int j = 0; j < 4; j++) {
            int idx = ss[j];
            unsigned int w = g_pack[idx >> 2];
            cc[j] = (w >> ((idx & 3) * 2)) & 3u;
            any |= cc[j];
        }
        if (any) {
            int4 d4 = *reinterpret_cast<const int4*>(dst + e);
            int dd[4] = {d4.x, d4.y, d4.z, d4.w};
#pragma unroll
            for (int j = 0; j < 4; j++) {
                unsigned int c = cc[j];
                if (c) {
                    int d = dd[j];
                    if (c == 1u) atomicAdd(&g_dge[d], __ldg(Qge + d));
                    else         atomicAdd(&g_dgi[d], __ldg(Qgi + d));
                }
            }
        }
    } else {
        for (; e < E; e++) {
            int idx = src[e];
            unsigned int c = (g_pack[idx >> 2] >> ((idx & 3) * 2)) & 3u;
            if (c) {
                int d = dst[e];
                if (c == 1u) atomicAdd(&g_dge[d], Qge[d]);
                else         atomicAdd(&g_dgi[d], Qgi[d]);
            }
        }
    }
}

// ---------------------------------------------------------------------------
// Kernel 3: AdEx neuron update, float4-vectorized (4 neurons/thread).
// Writes the 6 outputs and re-zeros the delta scratch for the next replay.
// ---------------------------------------------------------------------------
__global__ void neuron_kernel(
    const float4* __restrict__ voltage, const float4* __restrict__ adapt,
    const float4* __restrict__ ge_in,   const float4* __restrict__ gi_in,
    const float4* __restrict__ stim,    const float4* __restrict__ refr_in,
    const float4* __restrict__ g_L,     const float4* __restrict__ delta_T,
    const float4* __restrict__ v_thresh,const float4* __restrict__ v_rest,
    const float4* __restrict__ Cm,      const float4* __restrict__ aa,
    const float4* __restrict__ bb,      const float4* __restrict__ tau_w,
    const float4* __restrict__ tau_ge,  const float4* __restrict__ tau_gi,
    const float4* __restrict__ E_ge,    const float4* __restrict__ E_gi,
    const float4* __restrict__ I_bias,  const float4* __restrict__ stim_scale,
    const float4* __restrict__ v_cut,   const float4* __restrict__ v_reset,
    const float4* __restrict__ t_refrac,
    const float* __restrict__ dt_ptr,
    float* __restrict__ out, int n4) {
    int i = blockIdx.x * blockDim.x + threadIdx.x;
    if (i >= n4) return;
    int n = n4 * 4;

    float dt = __ldg(dt_ptr);

    float4 v4  = voltage[i];
    float4 w4  = adapt[i];
    float4 ge4 = ge_in[i];
    float4 gi4 = gi_in[i];
    float4 dge4 = *reinterpret_cast<const float4*>(g_dge + i * 4);
    float4 dgi4 = *reinterpret_cast<const float4*>(g_dgi + i * 4);
    *reinterpret_cast<float4*>(g_dge + i * 4) = make_float4(0.f, 0.f, 0.f, 0.f);
    *reinterpret_cast<float4*>(g_dgi + i * 4) = make_float4(0.f, 0.f, 0.f, 0.f);

    float4 gl4 = g_L[i];
    float4 dT4 = delta_T[i];
    float4 vt4 = v_thresh[i];
    float4 vr4 = v_rest[i];
    float4 C4  = Cm[i];
    float4 a4  = aa[i];
    float4 b4  = bb[i];
    float4 tw4 = tau_w[i];
    float4 tge4 = tau_ge[i];
    float4 tgi4 = tau_gi[i];
    float4 Ege4 = E_ge[i];
    float4 Egi4 = E_gi[i];
    float4 Ib4  = I_bias[i];
    float4 ssc4 = stim_scale[i];
    float4 st4  = stim[i];
    float4 vc4  = v_cut[i];
    float4 vrs4 = v_reset[i];
    float4 tr4  = t_refrac[i];
    float4 rf4  = refr_in[i];

    float4 vo, wo, geo, gio, ro, so;

#define LANE(F)                                                                 \
    {                                                                           \
        float v = v4.F, w = w4.F;                                               \
        float ge = ge4.F + dge4.F;                                              \
        float gi = gi4.F + dgi4.F;                                              \
        float gl = gl4.F, dT = dT4.F, vr = vr4.F;                               \
        float I = Ib4.F + ssc4.F * st4.F + ge * (Ege4.F - v) + gi * (Egi4.F - v); \
        float exp_term = gl * dT * expf(fminf((v - vt4.F) / dT, 20.0f));        \
        float dv = (-gl * (v - vr) + exp_term - w + I) / C4.F;                  \
        float dw = (-w + a4.F * (v - vr)) / tw4.F;                              \
        float refr = rf4.F;                                                     \
        float vn = (refr <= 0.0f) ? (v + dv * dt) : v;                          \
        float wn = w + dw * dt;                                                 \
        geo.F = ge - (ge / tge4.F) * dt;                                        \
        gio.F = gi - (gi / tgi4.F) * dt;                                        \
        bool spk = vn > vc4.F;                                                  \
        vo.F = spk ? vrs4.F : vn;                                               \
        wo.F = spk ? (wn + b4.F) : wn;                                          \
        ro.F = (spk ? tr4.F : refr) - dt;                                       \
        so.F = spk ? 1.0f : 0.0f;                                               \
    }
    LANE(x) LANE(y) LANE(z) LANE(w)
#undef LANE

    *reinterpret_cast<float4*>(out + 0 * n + i * 4) = vo;
    *reinterpret_cast<float4*>(out + 1 * n + i * 4) = wo;
    *reinterpret_cast<float4*>(out + 2 * n + i * 4) = geo;
    *reinterpret_cast<float4*>(out + 3 * n + i * 4) = gio;
    *reinterpret_cast<float4*>(out + 4 * n + i * 4) = ro;
    *reinterpret_cast<float4*>(out + 5 * n + i * 4) = so;
}

extern "C" void kernel_launch(void* const* d_in, const int* in_sizes, int n_in,
                              void* d_out, int out_size) {
    const float* voltage    = (const float*)d_in[0];
    const float* adapt      = (const float*)d_in[1];
    const float* ge         = (const float*)d_in[2];
    const float* gi         = (const float*)d_in[3];
    const float* stim       = (const float*)d_in[4];
    const float* refr       = (const float*)d_in[5];
    const float* g_L        = (const float*)d_in[6];
    const float* delta_T    = (const float*)d_in[7];
    const float* v_thresh   = (const float*)d_in[8];
    const float* v_rest     = (const float*)d_in[9];
    const float* C          = (const float*)d_in[10];
    const float* a          = (const float*)d_in[11];
    const float* b          = (const float*)d_in[12];
    const float* tau_w      = (const float*)d_in[13];
    const float* tau_ge     = (const float*)d_in[14];
    const float* tau_gi     = (const float*)d_in[15];
    const float* E_ge       = (const float*)d_in[16];
    const float* E_gi       = (const float*)d_in[17];
    const float* I_bias     = (const float*)d_in[18];
    const float* stim_scale = (const float*)d_in[19];
    const float* Q_ge       = (const float*)d_in[20];
    const float* Q_gi       = (const float*)d_in[21];
    const float* v_cut      = (const float*)d_in[22];
    const float* v_reset    = (const float*)d_in[23];
    const float* t_refrac   = (const float*)d_in[24];
    const float* spiked     = (const float*)d_in[25];
    const float* is_exc     = (const float*)d_in[26];
    const int*   edge_index = (const int*)d_in[27];
    const float* dt         = (const float*)d_in[28];

    int n = in_sizes[0];
    int n4 = n / 4;
    int E = in_sizes[27] / 2;
    const int* src = edge_index;
    const int* dst = edge_index + E;

    build_code_kernel<<<(n4 + 255) / 256, 256>>>(
        (const float4*)spiked, (const float4*)is_exc, n4);

    int edge_threads = (E + 3) / 4;
    edge_kernel<<<(edge_threads + 255) / 256, 256>>>(src, dst, Q_ge, Q_gi, E);

    neuron_kernel<<<(n4 + 255) / 256, 256>>>(
        (const float4*)voltage, (const float4*)adapt,
        (const float4*)ge, (const float4*)gi,
        (const float4*)stim, (const float4*)refr,
        (const float4*)g_L, (const float4*)delta_T,
        (const float4*)v_thresh, (const float4*)v_rest,
        (const float4*)C, (const float4*)a, (const float4*)b,
        (const float4*)tau_w, (const float4*)tau_ge, (const float4*)tau_gi,
        (const float4*)E_ge, (const float4*)E_gi,
        (const float4*)I_bias, (const float4*)stim_scale,
        (const float4*)v_cut, (const float4*)v_reset, (const float4*)t_refrac,
        dt, (float*)d_out, n4);
}

// round 4
// speedup vs baseline: 1.1269x; 1.0662x over previous
#include <cuda_runtime.h>
#include <cuda_bf16.h>

// Problem constants (fixed by dataset): N = 131072 neurons, E = N*64 edges.
#define MAX_N 131072

// Scratch: zero-initialized at module load; neuron kernel consumes AND re-zeros
// them each step so every graph replay starts from zero (deterministic).
__device__ float g_dge[MAX_N];
__device__ float g_dgi[MAX_N];
// Packed spike code: 2 bits per neuron (0 = silent, 1 = exc spike, 2 = inh spike).
// 32 KB total -> staged into shared memory by every edge block.
__device__ unsigned int g_pack[MAX_N / 16];

// ---------------------------------------------------------------------------
// Kernel 1: build packed per-neuron spike code. float4 loads, 4 neurons/thread,
// 4 threads cooperate on one packed word via __shfl. Bool inputs are float32.
// ---------------------------------------------------------------------------
__global__ void build_code_kernel(const float4* __restrict__ spiked4,
                                  const float4* __restrict__ is_exc4,
                                  int n4) {
    int i = blockIdx.x * blockDim.x + threadIdx.x;
    if (i >= n4) return;
    float4 s = spiked4[i];
    float4 x = is_exc4[i];
    unsigned int b = 0;
    b |= (s.x != 0.0f ? (x.x != 0.0f ? 1u : 2u) : 0u) << 0;
    b |= (s.y != 0.0f ? (x.y != 0.0f ? 1u : 2u) : 0u) << 2;
    b |= (s.z != 0.0f ? (x.z != 0.0f ? 1u : 2u) : 0u) << 4;
    b |= (s.w != 0.0f ? (x.w != 0.0f ? 1u : 2u) : 0u) << 6;
    // combine 4 threads' bytes into one uint32 (threads i, i+1, i+2, i+3)
    unsigned int b1 = __shfl_down_sync(0xffffffffu, b, 1);
    unsigned int b2 = __shfl_down_sync(0xffffffffu, b, 2);
    unsigned int b3 = __shfl_down_sync(0xffffffffu, b, 3);
    if ((i & 3) == 0)
        g_pack[i >> 2] = b | (b1 << 8) | (b2 << 16) | (b3 << 24);
}

// ---------------------------------------------------------------------------
// Kernel 2: event-driven synaptic scatter.
// The 32 KB code table is staged into shared memory; the 8.4M random gathers
// become LDS (conflict-degree ~4) instead of L1tex wavefront storms (~30/LDG).
// src/dst streamed as int4; dst loaded only when a group has an active source.
// ---------------------------------------------------------------------------
#define EDGE_BLOCK 1024
#define EDGE_EPT   8      // edges per thread
#define EDGE_PER_BLOCK (EDGE_BLOCK * EDGE_EPT)   // 8192

__global__ void __launch_bounds__(EDGE_BLOCK, 2)
edge_kernel(const int* __restrict__ src,
            const int* __restrict__ dst,
            const float* __restrict__ Qge,
            const float* __restrict__ Qgi,
            int E) {
    __shared__ unsigned int s_tab[MAX_N / 16];   // 32 KB

    int tid = threadIdx.x;
    // stage code table: 8192 words / 1024 threads = 2 uint4 per thread
    {
        const uint4* gp = reinterpret_cast<const uint4*>(g_pack);
        uint4* sp = reinterpret_cast<uint4*>(s_tab);
        sp[tid]              = gp[tid];
        sp[tid + EDGE_BLOCK] = gp[tid + EDGE_BLOCK];
    }
    __syncthreads();

    long base = (long)blockIdx.x * EDGE_PER_BLOCK;
    if (base + EDGE_PER_BLOCK <= E) {
        const int4* src4 = reinterpret_cast<const int4*>(src + base);
        const int4* dst4 = reinterpret_cast<const int4*>(dst + base);
        // front-batch src loads for MLP
        int4 s0 = src4[tid];
        int4 s1 = src4[tid + EDGE_BLOCK];
#pragma unroll
        for (int k = 0; k < 2; k++) {
            int4 s = (k == 0) ? s0 : s1;
            int ss[4] = {s.x, s.y, s.z, s.w};
            unsigned int cc[4];
            unsigned int any = 0;
#pragma unroll
            for (int j = 0; j < 4; j++) {
                int idx = ss[j];
                unsigned int w = s_tab[idx >> 4];
                cc[j] = (w >> ((idx & 15) * 2)) & 3u;
                any |= cc[j];
            }
            if (any) {
                int4 d4 = dst4[tid + k * EDGE_BLOCK];
                int dd[4] = {d4.x, d4.y, d4.z, d4.w};
#pragma unroll
                for (int j = 0; j < 4; j++) {
                    unsigned int c = cc[j];
                    if (c) {
                        int d = dd[j];
                        if (c == 1u) atomicAdd(&g_dge[d], __ldg(Qge + d));
                        else         atomicAdd(&g_dgi[d], __ldg(Qgi + d));
                    }
                }
            }
        }
    } else {
        for (long e = base + tid; e < E; e += EDGE_BLOCK) {
            int idx = src[e];
            unsigned int c = (s_tab[idx >> 4] >> ((idx & 15) * 2)) & 3u;
            if (c) {
                int d = dst[e];
                if (c == 1u) atomicAdd(&g_dge[d], Qge[d]);
                else         atomicAdd(&g_dgi[d], Qgi[d]);
            }
        }
    }
}

// ---------------------------------------------------------------------------
// Kernel 3: AdEx neuron update, float4-vectorized (4 neurons/thread).
// Writes the 6 outputs and re-zeros the delta scratch for the next replay.
// ---------------------------------------------------------------------------
__global__ void neuron_kernel(
    const float4* __restrict__ voltage, const float4* __restrict__ adapt,
    const float4* __restrict__ ge_in,   const float4* __restrict__ gi_in,
    const float4* __restrict__ stim,    const float4* __restrict__ refr_in,
    const float4* __restrict__ g_L,     const float4* __restrict__ delta_T,
    const float4* __restrict__ v_thresh,const float4* __restrict__ v_rest,
    const float4* __restrict__ Cm,      const float4* __restrict__ aa,
    const float4* __restrict__ bb,      const float4* __restrict__ tau_w,
    const float4* __restrict__ tau_ge,  const float4* __restrict__ tau_gi,
    const float4* __restrict__ E_ge,    const float4* __restrict__ E_gi,
    const float4* __restrict__ I_bias,  const float4* __restrict__ stim_scale,
    const float4* __restrict__ v_cut,   const float4* __restrict__ v_reset,
    const float4* __restrict__ t_refrac,
    const float* __restrict__ dt_ptr,
    float* __restrict__ out, int n4) {
    int i = blockIdx.x * blockDim.x + threadIdx.x;
    if (i >= n4) return;
    int n = n4 * 4;

    float dt = __ldg(dt_ptr);

    float4 v4  = voltage[i];
    float4 w4  = adapt[i];
    float4 ge4 = ge_in[i];
    float4 gi4 = gi_in[i];
    float4 dge4 = *reinterpret_cast<const float4*>(g_dge + i * 4);
    float4 dgi4 = *reinterpret_cast<const float4*>(g_dgi + i * 4);
    *reinterpret_cast<float4*>(g_dge + i * 4) = make_float4(0.f, 0.f, 0.f, 0.f);
    *reinterpret_cast<float4*>(g_dgi + i * 4) = make_float4(0.f, 0.f, 0.f, 0.f);

    float4 gl4 = g_L[i];
    float4 dT4 = delta_T[i];
    float4 vt4 = v_thresh[i];
    float4 vr4 = v_rest[i];
    float4 C4  = Cm[i];
    float4 a4  = aa[i];
    float4 b4  = bb[i];
    float4 tw4 = tau_w[i];
    float4 tge4 = tau_ge[i];
    float4 tgi4 = tau_gi[i];
    float4 Ege4 = E_ge[i];
    float4 Egi4 = E_gi[i];
    float4 Ib4  = I_bias[i];
    float4 ssc4 = stim_scale[i];
    float4 st4  = stim[i];
    float4 vc4  = v_cut[i];
    float4 vrs4 = v_reset[i];
    float4 tr4  = t_refrac[i];
    float4 rf4  = refr_in[i];

    float4 vo, wo, geo, gio, ro, so;

#define LANE(F)                                                                 \
    {                                                                           \
        float v = v4.F, w = w4.F;                                               \
        float ge = ge4.F + dge4.F;                                              \
        float gi = gi4.F + dgi4.F;                                              \
        float gl = gl4.F, dT = dT4.F, vr = vr4.F;                               \
        float I = Ib4.F + ssc4.F * st4.F + ge * (Ege4.F - v) + gi * (Egi4.F - v); \
        float exp_term = gl * dT * expf(fminf((v - vt4.F) / dT, 20.0f));        \
        float dv = (-gl * (v - vr) + exp_term - w + I) / C4.F;                  \
        float dw = (-w + a4.F * (v - vr)) / tw4.F;                              \
        float refr = rf4.F;                                                     \
        float vn = (refr <= 0.0f) ? (v + dv * dt) : v;                          \
        float wn = w + dw * dt;                                                 \
        geo.F = ge - (ge / tge4.F) * dt;                                        \
        gio.F = gi - (gi / tgi4.F) * dt;                                        \
        bool spk = vn > vc4.F;                                                  \
        vo.F = spk ? vrs4.F : vn;                                               \
        wo.F = spk ? (wn + b4.F) : wn;                                          \
        ro.F = (spk ? tr4.F : refr) - dt;                                       \
        so.F = spk ? 1.0f : 0.0f;                                               \
    }
    LANE(x) LANE(y) LANE(z) LANE(w)
#undef LANE

    *reinterpret_cast<float4*>(out + 0 * n + i * 4) = vo;
    *reinterpret_cast<float4*>(out + 1 * n + i * 4) = wo;
    *reinterpret_cast<float4*>(out + 2 * n + i * 4) = geo;
    *reinterpret_cast<float4*>(out + 3 * n + i * 4) = gio;
    *reinterpret_cast<float4*>(out + 4 * n + i * 4) = ro;
    *reinterpret_cast<float4*>(out + 5 * n + i * 4) = so;
}

extern "C" void kernel_launch(void* const* d_in, const int* in_sizes, int n_in,
                              void* d_out, int out_size) {
    const float* voltage    = (const float*)d_in[0];
    const float* adapt      = (const float*)d_in[1];
    const float* ge         = (const float*)d_in[2];
    const float* gi         = (const float*)d_in[3];
    const float* stim       = (const float*)d_in[4];
    const float* refr       = (const float*)d_in[5];
    const float* g_L        = (const float*)d_in[6];
    const float* delta_T    = (const float*)d_in[7];
    const float* v_thresh   = (const float*)d_in[8];
    const float* v_rest     = (const float*)d_in[9];
    const float* C          = (const float*)d_in[10];
    const float* a          = (const float*)d_in[11];
    const float* b          = (const float*)d_in[12];
    const float* tau_w      = (const float*)d_in[13];
    const float* tau_ge     = (const float*)d_in[14];
    const float* tau_gi     = (const float*)d_in[15];
    const float* E_ge       = (const float*)d_in[16];
    const float* E_gi       = (const float*)d_in[17];
    const float* I_bias     = (const float*)d_in[18];
    const float* stim_scale = (const float*)d_in[19];
    const float* Q_ge       = (const float*)d_in[20];
    const float* Q_gi       = (const float*)d_in[21];
    const float* v_cut      = (const float*)d_in[22];
    const float* v_reset    = (const float*)d_in[23];
    const float* t_refrac   = (const float*)d_in[24];
    const float* spiked     = (const float*)d_in[25];
    const float* is_exc     = (const float*)d_in[26];
    const int*   edge_index = (const int*)d_in[27];
    const float* dt         = (const float*)d_in[28];

    int n = in_sizes[0];
    int n4 = n / 4;
    int E = in_sizes[27] / 2;
    const int* src = edge_index;
    const int* dst = edge_index + E;

    // block=64 -> 512 blocks: full SM coverage for the tiny kernels
    build_code_kernel<<<(n4 + 63) / 64, 64>>>(
        (const float4*)spiked, (const float4*)is_exc, n4);

    int edge_blocks = (E + EDGE_PER_BLOCK - 1) / EDGE_PER_BLOCK;
    edge_kernel<<<edge_blocks, EDGE_BLOCK>>>(src, dst, Q_ge, Q_gi, E);

    neuron_kernel<<<(n4 + 63) / 64, 64>>>(
        (const float4*)voltage, (const float4*)adapt,
        (const float4*)ge, (const float4*)gi,
        (const float4*)stim, (const float4*)refr,
        (const float4*)g_L, (const float4*)delta_T,
        (const float4*)v_thresh, (const float4*)v_rest,
        (const float4*)C, (const float4*)a, (const float4*)b,
        (const float4*)tau_w, (const float4*)tau_ge, (const float4*)tau_gi,
        (const float4*)E_ge, (const float4*)E_gi,
        (const float4*)I_bias, (const float4*)stim_scale,
        (const float4*)v_cut, (const float4*)v_reset, (const float4*)t_refrac,
        dt, (float*)d_out, n4);
}